// round 16
// baseline (speedup 1.0000x reference)
#include <cuda_runtime.h>
#include <cuda_bf16.h>
#include <cuda_fp16.h>
#include <math.h>
#include <cstdint>

// Problem constants
#define BB 2
#define TT 2048
#define DM 1024
#define HH 16
#define DD 64
#define NQKV 5120     // H * 5 * D
#define BT  4096      // B * T
#define KW  2048      // GEMM operands: [hi(1024) | lo(1024)] bf16

// ---------------- scratch (no cudaMalloc allowed) ----------------
__device__ __align__(16) __nv_bfloat16 g_Ab[(size_t)BT * KW];          // 16.8 MB
__device__ __align__(16) __nv_bfloat16 g_Bq[(size_t)NQKV * KW];        // 21.0 MB
__device__ __align__(16) __nv_bfloat16 g_Bo[(size_t)DM * KW];          // 4.2 MB
// flash operands (fp16 single-plane): [bh][t][64], V^T [bh][d][t]
__device__ __align__(16) __half g_Q1f[(size_t)BB * HH * TT * DD];
__device__ __align__(16) __half g_Q2f[(size_t)BB * HH * TT * DD];
__device__ __align__(16) __half g_K1f[(size_t)BB * HH * TT * DD];
__device__ __align__(16) __half g_K2f[(size_t)BB * HH * TT * DD];
__device__ __align__(16) __half g_Vh [(size_t)BB * HH * TT * DD];      // V row-major fp16
__device__ __align__(16) __half g_Vt [(size_t)BB * HH * DD * TT];      // V^T

// ================= helpers (plain sm_103-safe PTX only) =================
__device__ __forceinline__ uint32_t smem_u32(const void* p) {
    uint32_t a;
    asm("{ .reg .u64 t; cvta.to.shared.u64 t, %1; cvt.u32.u64 %0, t; }" : "=r"(a) : "l"(p));
    return a;
}
#define CP16(smem, gptr) \
    asm volatile("cp.async.cg.shared.global [%0], [%1], 16;" :: "r"(smem), "l"(gptr) : "memory")
#define CP_COMMIT() asm volatile("cp.async.commit_group;" ::: "memory")
#define CP_WAIT(n)  asm volatile("cp.async.wait_group %0;" :: "n"(n) : "memory")
#define LDSM_X4(r0, r1, r2, r3, addr) \
    asm volatile("ldmatrix.sync.aligned.m8n8.x4.shared.b16 {%0,%1,%2,%3}, [%4];" \
                 : "=r"(r0), "=r"(r1), "=r"(r2), "=r"(r3) : "r"(addr))
#define MMA16816(c, a, b) \
    asm volatile("mma.sync.aligned.m16n8k16.row.col.f32.bf16.bf16.f32 " \
                 "{%0,%1,%2,%3}, {%4,%5,%6,%7}, {%8,%9}, {%0,%1,%2,%3};" \
                 : "+f"((c)[0]), "+f"((c)[1]), "+f"((c)[2]), "+f"((c)[3]) \
                 : "r"((a)[0]), "r"((a)[1]), "r"((a)[2]), "r"((a)[3]), \
                   "r"((b)[0]), "r"((b)[1]))
#define MMAH16816(c, a, b) \
    asm volatile("mma.sync.aligned.m16n8k16.row.col.f32.f16.f16.f32 " \
                 "{%0,%1,%2,%3}, {%4,%5,%6,%7}, {%8,%9}, {%0,%1,%2,%3};" \
                 : "+f"((c)[0]), "+f"((c)[1]), "+f"((c)[2]), "+f"((c)[3]) \
                 : "r"((a)[0]), "r"((a)[1]), "r"((a)[2]), "r"((a)[3]), \
                   "r"((b)[0]), "r"((b)[1]))

__device__ __forceinline__ uint32_t packbf(float lo, float hi) {
    __nv_bfloat162 t = __floats2bfloat162_rn(lo, hi);
    return *(uint32_t*)&t;
}
__device__ __forceinline__ uint32_t packh(float lo, float hi) {
    __half2 t = __floats2half2_rn(lo, hi);
    return *(uint32_t*)&t;
}

// ================= conversion kernels =================
// fp32 [M,1024] row-major -> bf16 [M,2048]: cols [0,1024)=hi [1024,2048)=lo
__global__ void __launch_bounds__(256) split_rows(const float* __restrict__ in,
                                                  __nv_bfloat16* __restrict__ out, int total) {
    int idx = blockIdx.x * 256 + threadIdx.x;
    if (idx >= total) return;
    int m = idx >> 10, k = idx & 1023;
    float v = in[idx];
    __nv_bfloat16 h = __float2bfloat16(v);
    __nv_bfloat16 l = __float2bfloat16(v - __bfloat162float(h));
    size_t rb = (size_t)m * KW;
    out[rb + k] = h;
    out[rb + 1024 + k] = l;
}

// W fp32 [1024, N] -> bf16 [N, 2048] transposed: cols [0,1024)=hi [1024,2048)=lo
__global__ void __launch_bounds__(256) splitT(const float* __restrict__ W,
                                              __nv_bfloat16* __restrict__ out, int N) {
    __shared__ float smt[32][33];
    int n0 = blockIdx.x * 32, k0 = blockIdx.y * 32;
    int tx = threadIdx.x, ty = threadIdx.y;  // 32 x 8
#pragma unroll
    for (int i = 0; i < 4; i++)
        smt[ty * 4 + i][tx] = W[(size_t)(k0 + ty * 4 + i) * N + n0 + tx];
    __syncthreads();
#pragma unroll
    for (int i = 0; i < 4; i++) {
        int nn = ty * 4 + i;
        float v = smt[tx][nn];
        __nv_bfloat16 h = __float2bfloat16(v);
        __nv_bfloat16 l = __float2bfloat16(v - __bfloat162float(h));
        size_t rb = (size_t)(n0 + nn) * KW + k0 + tx;
        out[rb] = h;
        out[rb + 1024] = l;
    }
}

// V fp16 [bh][t][64] -> V^T fp16 [bh][d][t]
__global__ void __launch_bounds__(256) v_transpose_h(const __half* __restrict__ Vh,
                                                     __half* __restrict__ Vt) {
    __shared__ __half tile[64][72];
    int t0 = blockIdx.x * 64;
    int bh = blockIdx.y;
    int c = threadIdx.x & 63, r4 = threadIdx.x >> 6;
#pragma unroll
    for (int rr = r4; rr < 64; rr += 4)
        tile[rr][c] = Vh[((size_t)bh * TT + t0 + rr) * DD + c];
    __syncthreads();
#pragma unroll
    for (int dd = r4; dd < 64; dd += 4)
        Vt[((size_t)bh * DD + dd) * TT + t0 + c] = tile[c][dd];
}

// ========== HMMA split-bf16 GEMM: C[M,N] = (Ahi+Alo)[M,1024] @ (Bhi+Blo)[N,1024]^T ==========
// 3-combo (hi*hi + hi*lo + lo*hi), 128x128 CTA tile, 32 warps (4m x 8n), warp tile 32x16.
// 1024 threads -> 8 warps/SMSP. 3-stage cp.async pipeline.
// MODE 0: write fp32 C. MODE 1: fan out fp16 q1/q2/k1/k2/v flash operands.
#define BKC 64
#define NKI (1024 / BKC)      // 16
#define ASTR 72               // smem row stride in bf16
#define TILE_E (128 * ASTR)   // one 128x64 tile (padded)
#define STAGE_E (4 * TILE_E)  // Ahi | Alo | Bhi | Blo
#define NSTAGE 3
#define GEMM_SMEM (NSTAGE * STAGE_E * 2)   // 221184 bytes
#define GT 1024

template <int MODE>
__global__ void __launch_bounds__(GT) gemm_mma(const __nv_bfloat16* __restrict__ A,
                                               const __nv_bfloat16* __restrict__ B,
                                               float* __restrict__ C, int Ntot,
                                               __half* __restrict__ Q1, __half* __restrict__ Q2,
                                               __half* __restrict__ K1, __half* __restrict__ K2,
                                               __half* __restrict__ Vh) {
    extern __shared__ __nv_bfloat16 smb[];
    const int tid = threadIdx.x;
    const int wid = tid >> 5;           // 0..31
    const int lane = tid & 31;
    const int m0 = blockIdx.y * 128;
    const int n0 = blockIdx.x * 128;
    const int wm = (wid >> 3) * 32;     // 0/32/64/96
    const int wn = (wid & 7) * 16;      // 0..112
    const uint32_t sbase = smem_u32(smb);

    // cp.async mapping: 1024 threads, 1x16B per tile per thread
    const int ldrow = tid >> 3;          // 0..127
    const int ldcol = (tid & 7) * 8;     // 0..56
    const __nv_bfloat16* Agp = A + (size_t)(m0 + ldrow) * KW + ldcol;
    const __nv_bfloat16* Bgp = B + (size_t)(n0 + ldrow) * KW + ldcol;
    const uint32_t st_off = (uint32_t)(ldrow * ASTR + ldcol) * 2;

    uint32_t aoff[2], boff;
#pragma unroll
    for (int mt = 0; mt < 2; mt++) {
        int row = wm + mt * 16 + (lane & 15);
        int col = (lane >> 4) * 8;
        aoff[mt] = (uint32_t)(row * ASTR + col) * 2;
    }
    {
        int n = wn + ((lane >> 4) & 1) * 8 + (lane & 7);
        int k = ((lane >> 3) & 1) * 8;
        boff = (uint32_t)(n * ASTR + k) * 2;
    }

    float acc[2][2][4];
#pragma unroll
    for (int mt = 0; mt < 2; mt++)
#pragma unroll
        for (int nt = 0; nt < 2; nt++)
#pragma unroll
            for (int j = 0; j < 4; j++) acc[mt][nt][j] = 0.f;

#define LOAD_STAGE(s, k0)                                                          \
    do {                                                                           \
        uint32_t _b = sbase + (uint32_t)(s) * STAGE_E * 2 + st_off;                \
        const __nv_bfloat16* _a = Agp + (k0);                                      \
        const __nv_bfloat16* _bb = Bgp + (k0);                                     \
        CP16(_b, _a);                                                              \
        CP16(_b + TILE_E * 2, _a + 1024);                                          \
        CP16(_b + 2 * TILE_E * 2, _bb);                                            \
        CP16(_b + 3 * TILE_E * 2, _bb + 1024);                                     \
    } while (0)

#define COMBO(afr, bfr)                                                            \
    do {                                                                           \
        _Pragma("unroll")                                                          \
        for (int mt = 0; mt < 2; mt++) {                                           \
            MMA16816(acc[mt][0], (afr)[mt], (&(bfr)[0]));                          \
            MMA16816(acc[mt][1], (afr)[mt], (&(bfr)[2]));                          \
        }                                                                          \
    } while (0)

    LOAD_STAGE(0, 0);
    CP_COMMIT();
    LOAD_STAGE(1, BKC);
    CP_COMMIT();

    for (int i = 0; i < NKI; i++) {
        if (i + 1 < NKI) { CP_WAIT(1); } else { CP_WAIT(0); }
        __syncthreads();
        if (i + 2 < NKI) {
            LOAD_STAGE((i + 2) % NSTAGE, (i + 2) * BKC);
            CP_COMMIT();
        }
        const uint32_t stAh = sbase + (uint32_t)(i % NSTAGE) * STAGE_E * 2;
        const uint32_t stAl = stAh + TILE_E * 2;
        const uint32_t stBh = stAh + 2 * TILE_E * 2;
        const uint32_t stBl = stAh + 3 * TILE_E * 2;
#pragma unroll
        for (int ks = 0; ks < 4; ks++) {
            uint32_t ah[2][4], al[2][4], bh[4], bl[4];
#pragma unroll
            for (int mt = 0; mt < 2; mt++) {
                LDSM_X4(ah[mt][0], ah[mt][1], ah[mt][2], ah[mt][3], stAh + aoff[mt] + ks * 32);
                LDSM_X4(al[mt][0], al[mt][1], al[mt][2], al[mt][3], stAl + aoff[mt] + ks * 32);
            }
            LDSM_X4(bh[0], bh[1], bh[2], bh[3], stBh + boff + ks * 32);
            LDSM_X4(bl[0], bl[1], bl[2], bl[3], stBl + boff + ks * 32);
            COMBO(ah, bh);
            COMBO(ah, bl);
            COMBO(al, bh);
        }
    }
#undef LOAD_STAGE
#undef COMBO

    if (MODE == 0) {
        // fp32 C epilogue (warp covers 16 cols)
#pragma unroll
        for (int mt = 0; mt < 2; mt++) {
            int r0 = m0 + wm + mt * 16 + (lane >> 2);
            int c0 = n0 + wn + (lane & 3) * 2;
            float* p0 = C + (size_t)r0 * Ntot + c0;
            float* p1 = C + (size_t)(r0 + 8) * Ntot + c0;
#pragma unroll
            for (int nt = 0; nt < 2; nt++) {
                *(float2*)(p0 + nt * 8) = make_float2(acc[mt][nt][0], acc[mt][nt][1]);
                *(float2*)(p1 + nt * 8) = make_float2(acc[mt][nt][2], acc[mt][nt][3]);
            }
        }
    } else {
        // QKV fan-out: warp's 16 cols lie inside one 64-col segment
        const int nglob = n0 + wn;
        const int seg = nglob >> 6;        // 0..79
        const int hd  = seg / 5;
        const int part = seg % 5;
        const int segoff = nglob & 63;     // 0/16/32/48
        __half* dst = (part == 0) ? Q1 : (part == 1) ? Q2 : (part == 2) ? K1
                     : (part == 3) ? K2 : Vh;
        const int dcol = segoff + (lane & 3) * 2;
#pragma unroll
        for (int mt = 0; mt < 2; mt++) {
            int r0 = m0 + wm + mt * 16 + (lane >> 2);
#pragma unroll
            for (int half = 0; half < 2; half++) {
                int row = r0 + half * 8;
                int b = row >> 11, t = row & (TT - 1);
                size_t base = ((size_t)(b * HH + hd) * TT + t) * DD + dcol;
#pragma unroll
                for (int nt = 0; nt < 2; nt++) {
                    uint32_t hv = packh(acc[mt][nt][2 * half], acc[mt][nt][2 * half + 1]);
                    *(uint32_t*)&dst[base + nt * 8] = hv;
                }
            }
        }
    }
}

// ================= fp16 HMMA dual flash attention =================
// CTA: 128 q-rows of one (b,h); 8 warps, warp = m16. kv tiles of 64, double-buffered.
// launch_bounds(256, 2): cap 128 regs -> 2 CTAs/SM resident.
#define QS2 72                        // fp16 row stride (144B)
#define FL_Q1 0
#define FL_Q2 (128 * QS2)
#define FL_ST0 (2 * 128 * QS2)
#define FL_KV (64 * QS2)              // one tensor in a stage
#define FL_STAGE (3 * FL_KV)          // K1 | K2 | Vt
#define FL_SMEM_BYTES ((2 * 128 * QS2 + 2 * FL_STAGE) * 2)   // 92160

__device__ __forceinline__ void fl_load_kv(uint32_t sb, int st, int kt, int tid,
                                           const __half* K1g,
                                           const __half* K2g,
                                           const __half* Vg) {
    int r = tid >> 2, qd = tid & 3;   // row 0..63, 16-elem quarter
    uint32_t base = sb + (uint32_t)(FL_ST0 + st * FL_STAGE) * 2;
    uint32_t o = (uint32_t)(r * QS2 + qd * 16) * 2;
    const __half* k1 = K1g + (size_t)(kt * 64 + r) * DD + qd * 16;
    const __half* k2 = K2g + (size_t)(kt * 64 + r) * DD + qd * 16;
    const __half* vv = Vg + (size_t)r * TT + kt * 64 + qd * 16;
#pragma unroll
    for (int j = 0; j < 2; j++) {
        CP16(base + o + j * 16, k1 + j * 8);
        CP16(base + FL_KV * 2 + o + j * 16, k2 + j * 8);
        CP16(base + 2 * FL_KV * 2 + o + j * 16, vv + j * 8);
    }
}

// one stream: S = Q K^T (fp16), online softmax, O += P V (fp16)
__device__ __forceinline__ void fl_stream(uint32_t a_addr, uint32_t kstage, uint32_t vstage,
                                          uint32_t b_lane_b, int kt, bool need_mask,
                                          int row_g0, int lane,
                                          float O[8][4], float* mst, float* lst) {
    float acc[8][4];
#pragma unroll
    for (int nb = 0; nb < 8; nb++)
#pragma unroll
        for (int j = 0; j < 4; j++) acc[nb][j] = 0.f;

    // S = Q K^T, 4 k16 steps over D=64
#pragma unroll
    for (int s = 0; s < 4; s++) {
        uint32_t af[4];
        LDSM_X4(af[0], af[1], af[2], af[3], a_addr + s * 32);
#pragma unroll
        for (int nt2 = 0; nt2 < 4; nt2++) {
            uint32_t bf[4];
            LDSM_X4(bf[0], bf[1], bf[2], bf[3],
                    kstage + b_lane_b + (uint32_t)(nt2 * 16 * QS2 + s * 16) * 2);
            MMAH16816(acc[2 * nt2],     af, (&bf[0]));
            MMAH16816(acc[2 * nt2 + 1], af, (&bf[2]));
        }
    }

    // scale + causal mask
#pragma unroll
    for (int nb = 0; nb < 8; nb++)
#pragma unroll
        for (int j = 0; j < 4; j++) {
            float v = acc[nb][j] * 0.125f;
            if (need_mask) {
                int col = kt * 64 + nb * 8 + 2 * (lane & 3) + (j & 1);
                int row = row_g0 + ((j >> 1) << 3);
                if (col > row) v = -1e30f;
            }
            acc[nb][j] = v;
        }

    // online softmax (rows r and r+8)
    float mx0 = -1e30f, mx1 = -1e30f;
#pragma unroll
    for (int nb = 0; nb < 8; nb++) {
        mx0 = fmaxf(mx0, fmaxf(acc[nb][0], acc[nb][1]));
        mx1 = fmaxf(mx1, fmaxf(acc[nb][2], acc[nb][3]));
    }
    mx0 = fmaxf(mx0, __shfl_xor_sync(0xffffffffu, mx0, 1));
    mx0 = fmaxf(mx0, __shfl_xor_sync(0xffffffffu, mx0, 2));
    mx1 = fmaxf(mx1, __shfl_xor_sync(0xffffffffu, mx1, 1));
    mx1 = fmaxf(mx1, __shfl_xor_sync(0xffffffffu, mx1, 2));
    float mn0 = fmaxf(mst[0], mx0), mn1 = fmaxf(mst[1], mx1);
    float al0 = __expf(mst[0] - mn0), al1 = __expf(mst[1] - mn1);
    float s0 = 0.f, s1 = 0.f;
#pragma unroll
    for (int nb = 0; nb < 8; nb++) {
        acc[nb][0] = __expf(acc[nb][0] - mn0);
        acc[nb][1] = __expf(acc[nb][1] - mn0);
        acc[nb][2] = __expf(acc[nb][2] - mn1);
        acc[nb][3] = __expf(acc[nb][3] - mn1);
        s0 += acc[nb][0] + acc[nb][1];
        s1 += acc[nb][2] + acc[nb][3];
    }
    s0 += __shfl_xor_sync(0xffffffffu, s0, 1);
    s0 += __shfl_xor_sync(0xffffffffu, s0, 2);
    s1 += __shfl_xor_sync(0xffffffffu, s1, 1);
    s1 += __shfl_xor_sync(0xffffffffu, s1, 2);
    lst[0] = lst[0] * al0 + s0;
    lst[1] = lst[1] * al1 + s1;
    mst[0] = mn0;
    mst[1] = mn1;
#pragma unroll
    for (int nb = 0; nb < 8; nb++) {
        O[nb][0] *= al0; O[nb][1] *= al0;
        O[nb][2] *= al1; O[nb][3] *= al1;
    }

    // O += P V (register-direct fp16 P fragments)
#pragma unroll
    for (int s = 0; s < 4; s++) {
        uint32_t ah[4];
        ah[0] = packh(acc[2 * s][0],     acc[2 * s][1]);
        ah[1] = packh(acc[2 * s][2],     acc[2 * s][3]);
        ah[2] = packh(acc[2 * s + 1][0], acc[2 * s + 1][1]);
        ah[3] = packh(acc[2 * s + 1][2], acc[2 * s + 1][3]);
#pragma unroll
        for (int nt2 = 0; nt2 < 4; nt2++) {
            uint32_t bv[4];
            LDSM_X4(bv[0], bv[1], bv[2], bv[3],
                    vstage + b_lane_b + (uint32_t)(nt2 * 16 * QS2 + s * 16) * 2);
            MMAH16816(O[2 * nt2],     ah, (&bv[0]));
            MMAH16816(O[2 * nt2 + 1], ah, (&bv[2]));
        }
    }
}

__global__ void __launch_bounds__(256, 2) flash_mma(
    const __half* __restrict__ Q1f, const __half* __restrict__ Q2f,
    const __half* __restrict__ K1f, const __half* __restrict__ K2f,
    const __half* __restrict__ Vtg, const float* __restrict__ lam_p,
    __nv_bfloat16* __restrict__ Ab) {
    extern __shared__ __half sfb[];
    const uint32_t sb = smem_u32(sfb);
    const int tid = threadIdx.x, wid = tid >> 5, lane = tid & 31;
    const int qrev = gridDim.x - 1 - blockIdx.x;    // heavy CTAs first
    const int q0 = qrev * 128;
    const int h = blockIdx.y, b = blockIdx.z;
    const int bh = b * HH + h;
    const int nkv = 2 * qrev + 2;

    const __half* Q1g = Q1f + ((size_t)bh * TT + q0) * DD;
    const __half* Q2g = Q2f + ((size_t)bh * TT + q0) * DD;
    const __half* K1g = K1f + (size_t)bh * TT * DD;
    const __half* K2g = K2f + (size_t)bh * TT * DD;
    const __half* Vg  = Vtg + (size_t)bh * DD * TT;

    // Q tiles via cp.async: 128 rows x 64 fp16
    {
        int row = tid >> 1, seg = (tid & 1) * 32;
        uint32_t d1 = sb + (uint32_t)(FL_Q1 + row * QS2 + seg) * 2;
        uint32_t d2 = sb + (uint32_t)(FL_Q2 + row * QS2 + seg) * 2;
        const __half* s1 = Q1g + row * DD + seg;
        const __half* s2 = Q2g + row * DD + seg;
#pragma unroll
        for (int j = 0; j < 4; j++) { CP16(d1 + j * 16, s1 + j * 8); CP16(d2 + j * 16, s2 + j * 8); }
    }
    fl_load_kv(sb, 0, 0, tid, K1g, K2g, Vg);
    CP_COMMIT();

    float O1[8][4], O2[8][4];
#pragma unroll
    for (int nb = 0; nb < 8; nb++)
#pragma unroll
        for (int j = 0; j < 4; j++) { O1[nb][j] = 0.f; O2[nb][j] = 0.f; }
    float m1[2] = {-1e30f, -1e30f}, l1[2] = {0.f, 0.f};
    float m2[2] = {-1e30f, -1e30f}, l2[2] = {0.f, 0.f};

    const int row_g0 = q0 + wid * 16 + (lane >> 2);
    const uint32_t a_lane = (uint32_t)((lane & 15) * QS2 + (lane >> 4) * 8) * 2;
    const uint32_t aQ1 = sb + (uint32_t)(FL_Q1 + wid * 16 * QS2) * 2 + a_lane;
    const uint32_t aQ2 = sb + (uint32_t)(FL_Q2 + wid * 16 * QS2) * 2 + a_lane;
    const uint32_t b_lane_b = (uint32_t)((((lane >> 4) & 1) * 8 + (lane & 7)) * QS2 +
                                         ((lane >> 3) & 1) * 8) * 2;

    for (int kt = 0; kt < nkv; kt++) {
        if (kt + 1 < nkv) {
            fl_load_kv(sb, (kt + 1) & 1, kt + 1, tid, K1g, K2g, Vg);
            CP_COMMIT();
            CP_WAIT(1);
        } else {
            CP_WAIT(0);
        }
        __syncthreads();
        const uint32_t st = sb + (uint32_t)(FL_ST0 + (kt & 1) * FL_STAGE) * 2;
        const bool msk = (kt >= nkv - 2);
        fl_stream(aQ1, st,             st + 2 * FL_KV * 2, b_lane_b, kt, msk, row_g0, lane, O1, m1, l1);
        fl_stream(aQ2, st + FL_KV * 2, st + 2 * FL_KV * 2, b_lane_b, kt, msk, row_g0, lane, O2, m2, l2);
        __syncthreads();
    }

    // epilogue: out = O1/l1 - lam*O2/l2, write split-bf16 [hi|lo] into Ab
    float lamv = fminf(fmaxf(lam_p[h], 0.f), 1.f);
    float i10 = 1.f / l1[0], i11 = 1.f / l1[1];
    float i20 = lamv / l2[0], i21 = lamv / l2[1];
    const int row0 = q0 + wid * 16 + (lane >> 2);
    const int colb = h * 64 + 2 * (lane & 3);
    size_t rb0 = (size_t)(b * TT + row0) * KW;
    size_t rb1 = (size_t)(b * TT + row0 + 8) * KW;
#pragma unroll
    for (int nb = 0; nb < 8; nb++) {
        int col = colb + nb * 8;
        float x0 = O1[nb][0] * i10 - O2[nb][0] * i20;
        float x1 = O1[nb][1] * i10 - O2[nb][1] * i20;
        float y0 = O1[nb][2] * i11 - O2[nb][2] * i21;
        float y1 = O1[nb][3] * i11 - O2[nb][3] * i21;
        uint32_t hx = packbf(x0, x1);
        __nv_bfloat162 hv = *(__nv_bfloat162*)&hx;
        float2 hf = __bfloat1622float2(hv);
        uint32_t lx = packbf(x0 - hf.x, x1 - hf.y);
        *(uint32_t*)&Ab[rb0 + col] = hx;
        *(uint32_t*)&Ab[rb0 + 1024 + col] = lx;
        uint32_t hy = packbf(y0, y1);
        __nv_bfloat162 hv2 = *(__nv_bfloat162*)&hy;
        float2 hf2 = __bfloat1622float2(hv2);
        uint32_t ly = packbf(y0 - hf2.x, y1 - hf2.y);
        *(uint32_t*)&Ab[rb1 + col] = hy;
        *(uint32_t*)&Ab[rb1 + 1024 + col] = ly;
    }
}

// ---------------- launch ----------------
extern "C" void kernel_launch(void* const* d_in, const int* in_sizes, int n_in,
                              void* d_out, int out_size) {
    const float* x    = (const float*)d_in[0];
    const float* Wqkv = (const float*)d_in[2];
    const float* Wout = (const float*)d_in[3];
    const float* lam  = (const float*)d_in[4];
    float* out = (float*)d_out;

    __nv_bfloat16 *Ab = nullptr, *Bq = nullptr, *Bo = nullptr;
    __half *Q1f = nullptr, *Q2f = nullptr, *K1f = nullptr, *K2f = nullptr;
    __half *Vh = nullptr, *Vt = nullptr;
    cudaGetSymbolAddress((void**)&Ab,  g_Ab);
    cudaGetSymbolAddress((void**)&Bq,  g_Bq);
    cudaGetSymbolAddress((void**)&Bo,  g_Bo);
    cudaGetSymbolAddress((void**)&Q1f, g_Q1f);
    cudaGetSymbolAddress((void**)&Q2f, g_Q2f);
    cudaGetSymbolAddress((void**)&K1f, g_K1f);
    cudaGetSymbolAddress((void**)&K2f, g_K2f);
    cudaGetSymbolAddress((void**)&Vh,  g_Vh);
    cudaGetSymbolAddress((void**)&Vt,  g_Vt);

    cudaFuncSetAttribute(gemm_mma<0>, cudaFuncAttributeMaxDynamicSharedMemorySize, GEMM_SMEM);
    cudaFuncSetAttribute(gemm_mma<1>, cudaFuncAttributeMaxDynamicSharedMemorySize, GEMM_SMEM);
    cudaFuncSetAttribute(flash_mma, cudaFuncAttributeMaxDynamicSharedMemorySize, FL_SMEM_BYTES);

    // weight + input split conversions
    splitT<<<dim3(NQKV / 32, DM / 32), dim3(32, 8)>>>(Wqkv, Bq, NQKV);
    splitT<<<dim3(DM / 32, DM / 32), dim3(32, 8)>>>(Wout, Bo, DM);
    split_rows<<<(BT * DM + 255) / 256, 256>>>(x, Ab, BT * DM);

    // 1) QKV projection (bf16 3-combo, 32 warps/CTA) + fused fp16 fan-out
    gemm_mma<1><<<dim3(NQKV / 128, BT / 128), GT, GEMM_SMEM>>>(
        Ab, Bq, nullptr, NQKV, Q1f, Q2f, K1f, K2f, Vh);

    // 2) V transpose (fp16 -> fp16)
    v_transpose_h<<<dim3(TT / 64, BB * HH), 256>>>(Vh, Vt);

    // 3) dual flash attention (fp16 HMMA, 2 CTAs/SM); writes split-bf16 attn into Ab
    flash_mma<<<dim3(TT / 128, HH, BB), 256, FL_SMEM_BYTES>>>(Q1f, Q2f, K1f, K2f, Vt, lam, Ab);

    // 4) output projection (bf16 3-combo, 32 warps/CTA), fp32 C
    gemm_mma<0><<<dim3(DM / 128, BT / 128), GT, GEMM_SMEM>>>(
        Ab, Bo, out, DM, nullptr, nullptr, nullptr, nullptr, nullptr);
}

// round 17
// speedup vs baseline: 1.2294x; 1.2294x over previous
#include <cuda_runtime.h>
#include <cuda_bf16.h>
#include <cuda_fp16.h>
#include <math.h>
#include <cstdint>

// Problem constants
#define BB 2
#define TT 2048
#define DM 1024
#define HH 16
#define DD 64
#define NQKV 5120     // H * 5 * D
#define BT  4096      // B * T
#define KW  2048      // GEMM operands: [hi(1024) | lo(1024)] bf16

// ---------------- scratch (no cudaMalloc allowed) ----------------
__device__ __align__(16) __nv_bfloat16 g_Ab[(size_t)BT * KW];          // 16.8 MB
__device__ __align__(16) __nv_bfloat16 g_Bq[(size_t)NQKV * KW];        // 21.0 MB
__device__ __align__(16) __nv_bfloat16 g_Bo[(size_t)DM * KW];          // 4.2 MB
// flash operands (fp16 single-plane): [bh][t][64], V^T [bh][d][t]
__device__ __align__(16) __half g_Q1f[(size_t)BB * HH * TT * DD];
__device__ __align__(16) __half g_Q2f[(size_t)BB * HH * TT * DD];
__device__ __align__(16) __half g_K1f[(size_t)BB * HH * TT * DD];
__device__ __align__(16) __half g_K2f[(size_t)BB * HH * TT * DD];
__device__ __align__(16) __half g_Vh [(size_t)BB * HH * TT * DD];      // V row-major fp16
__device__ __align__(16) __half g_Vt [(size_t)BB * HH * DD * TT];      // V^T

// ================= helpers (plain sm_103-safe PTX only) =================
__device__ __forceinline__ uint32_t smem_u32(const void* p) {
    uint32_t a;
    asm("{ .reg .u64 t; cvta.to.shared.u64 t, %1; cvt.u32.u64 %0, t; }" : "=r"(a) : "l"(p));
    return a;
}
#define CP16(smem, gptr) \
    asm volatile("cp.async.cg.shared.global [%0], [%1], 16;" :: "r"(smem), "l"(gptr) : "memory")
#define CP_COMMIT() asm volatile("cp.async.commit_group;" ::: "memory")
#define CP_WAIT(n)  asm volatile("cp.async.wait_group %0;" :: "n"(n) : "memory")
#define LDSM_X4(r0, r1, r2, r3, addr) \
    asm volatile("ldmatrix.sync.aligned.m8n8.x4.shared.b16 {%0,%1,%2,%3}, [%4];" \
                 : "=r"(r0), "=r"(r1), "=r"(r2), "=r"(r3) : "r"(addr))
#define MMA16816(c, a, b) \
    asm volatile("mma.sync.aligned.m16n8k16.row.col.f32.bf16.bf16.f32 " \
                 "{%0,%1,%2,%3}, {%4,%5,%6,%7}, {%8,%9}, {%0,%1,%2,%3};" \
                 : "+f"((c)[0]), "+f"((c)[1]), "+f"((c)[2]), "+f"((c)[3]) \
                 : "r"((a)[0]), "r"((a)[1]), "r"((a)[2]), "r"((a)[3]), \
                   "r"((b)[0]), "r"((b)[1]))
#define MMAH16816(c, a, b) \
    asm volatile("mma.sync.aligned.m16n8k16.row.col.f32.f16.f16.f32 " \
                 "{%0,%1,%2,%3}, {%4,%5,%6,%7}, {%8,%9}, {%0,%1,%2,%3};" \
                 : "+f"((c)[0]), "+f"((c)[1]), "+f"((c)[2]), "+f"((c)[3]) \
                 : "r"((a)[0]), "r"((a)[1]), "r"((a)[2]), "r"((a)[3]), \
                   "r"((b)[0]), "r"((b)[1]))

__device__ __forceinline__ uint32_t packbf(float lo, float hi) {
    __nv_bfloat162 t = __floats2bfloat162_rn(lo, hi);
    return *(uint32_t*)&t;
}
__device__ __forceinline__ uint32_t packh(float lo, float hi) {
    __half2 t = __floats2half2_rn(lo, hi);
    return *(uint32_t*)&t;
}

// ================= conversion kernels =================
// fp32 [M,1024] row-major -> bf16 [M,2048]: cols [0,1024)=hi [1024,2048)=lo
__global__ void __launch_bounds__(256) split_rows(const float* __restrict__ in,
                                                  __nv_bfloat16* __restrict__ out, int total) {
    int idx = blockIdx.x * 256 + threadIdx.x;
    if (idx >= total) return;
    int m = idx >> 10, k = idx & 1023;
    float v = in[idx];
    __nv_bfloat16 h = __float2bfloat16(v);
    __nv_bfloat16 l = __float2bfloat16(v - __bfloat162float(h));
    size_t rb = (size_t)m * KW;
    out[rb + k] = h;
    out[rb + 1024 + k] = l;
}

// W fp32 [1024, N] -> bf16 [N, 2048] transposed: cols [0,1024)=hi [1024,2048)=lo
__global__ void __launch_bounds__(256) splitT(const float* __restrict__ W,
                                              __nv_bfloat16* __restrict__ out, int N) {
    __shared__ float smt[32][33];
    int n0 = blockIdx.x * 32, k0 = blockIdx.y * 32;
    int tx = threadIdx.x, ty = threadIdx.y;  // 32 x 8
#pragma unroll
    for (int i = 0; i < 4; i++)
        smt[ty * 4 + i][tx] = W[(size_t)(k0 + ty * 4 + i) * N + n0 + tx];
    __syncthreads();
#pragma unroll
    for (int i = 0; i < 4; i++) {
        int nn = ty * 4 + i;
        float v = smt[tx][nn];
        __nv_bfloat16 h = __float2bfloat16(v);
        __nv_bfloat16 l = __float2bfloat16(v - __bfloat162float(h));
        size_t rb = (size_t)(n0 + nn) * KW + k0 + tx;
        out[rb] = h;
        out[rb + 1024] = l;
    }
}

// V fp16 [bh][t][64] -> V^T fp16 [bh][d][t]
__global__ void __launch_bounds__(256) v_transpose_h(const __half* __restrict__ Vh,
                                                     __half* __restrict__ Vt) {
    __shared__ __half tile[64][72];
    int t0 = blockIdx.x * 64;
    int bh = blockIdx.y;
    int c = threadIdx.x & 63, r4 = threadIdx.x >> 6;
#pragma unroll
    for (int rr = r4; rr < 64; rr += 4)
        tile[rr][c] = Vh[((size_t)bh * TT + t0 + rr) * DD + c];
    __syncthreads();
#pragma unroll
    for (int dd = r4; dd < 64; dd += 4)
        Vt[((size_t)bh * DD + dd) * TT + t0 + c] = tile[c][dd];
}

// ========== HMMA split-bf16 GEMM: C[M,N] = (Ahi+Alo)[M,1024] @ (Bhi+Blo)[N,1024]^T ==========
// 3-combo (hi*hi + hi*lo + lo*hi), 128x128 CTA tile, 32 warps (4m x 8n), warp tile 32x16.
// 1024 threads -> 8 warps/SMSP. 3-stage cp.async pipeline.
// MODE 0: write fp32 C. MODE 1: fan out fp16 q1/q2/k1/k2/v flash operands.
#define BKC 64
#define NKI (1024 / BKC)      // 16
#define ASTR 72               // smem row stride in bf16
#define TILE_E (128 * ASTR)   // one 128x64 tile (padded)
#define STAGE_E (4 * TILE_E)  // Ahi | Alo | Bhi | Blo
#define NSTAGE 3
#define GEMM_SMEM (NSTAGE * STAGE_E * 2)   // 221184 bytes
#define GT 1024

template <int MODE>
__global__ void __launch_bounds__(GT) gemm_mma(const __nv_bfloat16* __restrict__ A,
                                               const __nv_bfloat16* __restrict__ B,
                                               float* __restrict__ C, int Ntot,
                                               __half* __restrict__ Q1, __half* __restrict__ Q2,
                                               __half* __restrict__ K1, __half* __restrict__ K2,
                                               __half* __restrict__ Vh) {
    extern __shared__ __nv_bfloat16 smb[];
    const int tid = threadIdx.x;
    const int wid = tid >> 5;           // 0..31
    const int lane = tid & 31;
    const int m0 = blockIdx.y * 128;
    const int n0 = blockIdx.x * 128;
    const int wm = (wid >> 3) * 32;     // 0/32/64/96
    const int wn = (wid & 7) * 16;      // 0..112
    const uint32_t sbase = smem_u32(smb);

    // cp.async mapping: 1024 threads, 1x16B per tile per thread
    const int ldrow = tid >> 3;          // 0..127
    const int ldcol = (tid & 7) * 8;     // 0..56
    const __nv_bfloat16* Agp = A + (size_t)(m0 + ldrow) * KW + ldcol;
    const __nv_bfloat16* Bgp = B + (size_t)(n0 + ldrow) * KW + ldcol;
    const uint32_t st_off = (uint32_t)(ldrow * ASTR + ldcol) * 2;

    uint32_t aoff[2], boff;
#pragma unroll
    for (int mt = 0; mt < 2; mt++) {
        int row = wm + mt * 16 + (lane & 15);
        int col = (lane >> 4) * 8;
        aoff[mt] = (uint32_t)(row * ASTR + col) * 2;
    }
    {
        int n = wn + ((lane >> 4) & 1) * 8 + (lane & 7);
        int k = ((lane >> 3) & 1) * 8;
        boff = (uint32_t)(n * ASTR + k) * 2;
    }

    float acc[2][2][4];
#pragma unroll
    for (int mt = 0; mt < 2; mt++)
#pragma unroll
        for (int nt = 0; nt < 2; nt++)
#pragma unroll
            for (int j = 0; j < 4; j++) acc[mt][nt][j] = 0.f;

#define LOAD_STAGE(s, k0)                                                          \
    do {                                                                           \
        uint32_t _b = sbase + (uint32_t)(s) * STAGE_E * 2 + st_off;                \
        const __nv_bfloat16* _a = Agp + (k0);                                      \
        const __nv_bfloat16* _bb = Bgp + (k0);                                     \
        CP16(_b, _a);                                                              \
        CP16(_b + TILE_E * 2, _a + 1024);                                          \
        CP16(_b + 2 * TILE_E * 2, _bb);                                            \
        CP16(_b + 3 * TILE_E * 2, _bb + 1024);                                     \
    } while (0)

#define COMBO(afr, bfr)                                                            \
    do {                                                                           \
        _Pragma("unroll")                                                          \
        for (int mt = 0; mt < 2; mt++) {                                           \
            MMA16816(acc[mt][0], (afr)[mt], (&(bfr)[0]));                          \
            MMA16816(acc[mt][1], (afr)[mt], (&(bfr)[2]));                          \
        }                                                                          \
    } while (0)

    LOAD_STAGE(0, 0);
    CP_COMMIT();
    LOAD_STAGE(1, BKC);
    CP_COMMIT();

    for (int i = 0; i < NKI; i++) {
        if (i + 1 < NKI) { CP_WAIT(1); } else { CP_WAIT(0); }
        __syncthreads();
        if (i + 2 < NKI) {
            LOAD_STAGE((i + 2) % NSTAGE, (i + 2) * BKC);
            CP_COMMIT();
        }
        const uint32_t stAh = sbase + (uint32_t)(i % NSTAGE) * STAGE_E * 2;
        const uint32_t stAl = stAh + TILE_E * 2;
        const uint32_t stBh = stAh + 2 * TILE_E * 2;
        const uint32_t stBl = stAh + 3 * TILE_E * 2;
#pragma unroll
        for (int ks = 0; ks < 4; ks++) {
            uint32_t ah[2][4], al[2][4], bh[4], bl[4];
#pragma unroll
            for (int mt = 0; mt < 2; mt++) {
                LDSM_X4(ah[mt][0], ah[mt][1], ah[mt][2], ah[mt][3], stAh + aoff[mt] + ks * 32);
                LDSM_X4(al[mt][0], al[mt][1], al[mt][2], al[mt][3], stAl + aoff[mt] + ks * 32);
            }
            LDSM_X4(bh[0], bh[1], bh[2], bh[3], stBh + boff + ks * 32);
            LDSM_X4(bl[0], bl[1], bl[2], bl[3], stBl + boff + ks * 32);
            COMBO(ah, bh);
            COMBO(ah, bl);
            COMBO(al, bh);
        }
    }
#undef LOAD_STAGE
#undef COMBO

    if (MODE == 0) {
        // fp32 C epilogue (warp covers 16 cols)
#pragma unroll
        for (int mt = 0; mt < 2; mt++) {
            int r0 = m0 + wm + mt * 16 + (lane >> 2);
            int c0 = n0 + wn + (lane & 3) * 2;
            float* p0 = C + (size_t)r0 * Ntot + c0;
            float* p1 = C + (size_t)(r0 + 8) * Ntot + c0;
#pragma unroll
            for (int nt = 0; nt < 2; nt++) {
                *(float2*)(p0 + nt * 8) = make_float2(acc[mt][nt][0], acc[mt][nt][1]);
                *(float2*)(p1 + nt * 8) = make_float2(acc[mt][nt][2], acc[mt][nt][3]);
            }
        }
    } else {
        // QKV fan-out: warp's 16 cols lie inside one 64-col segment
        const int nglob = n0 + wn;
        const int seg = nglob >> 6;        // 0..79
        const int hd  = seg / 5;
        const int part = seg % 5;
        const int segoff = nglob & 63;     // 0/16/32/48
        __half* dst = (part == 0) ? Q1 : (part == 1) ? Q2 : (part == 2) ? K1
                     : (part == 3) ? K2 : Vh;
        const int dcol = segoff + (lane & 3) * 2;
#pragma unroll
        for (int mt = 0; mt < 2; mt++) {
            int r0 = m0 + wm + mt * 16 + (lane >> 2);
#pragma unroll
            for (int half = 0; half < 2; half++) {
                int row = r0 + half * 8;
                int b = row >> 11, t = row & (TT - 1);
                size_t base = ((size_t)(b * HH + hd) * TT + t) * DD + dcol;
#pragma unroll
                for (int nt = 0; nt < 2; nt++) {
                    uint32_t hv = packh(acc[mt][nt][2 * half], acc[mt][nt][2 * half + 1]);
                    *(uint32_t*)&dst[base + nt * 8] = hv;
                }
            }
        }
    }
}

// ================= fp16 HMMA dual flash attention =================
// CTA: 128 q-rows of one (b,h); 8 warps, warp = m16. kv tiles of 64, double-buffered.
#define QS2 72                        // fp16 row stride (144B)
#define FL_Q1 0
#define FL_Q2 (128 * QS2)
#define FL_ST0 (2 * 128 * QS2)
#define FL_KV (64 * QS2)              // one tensor in a stage
#define FL_STAGE (3 * FL_KV)          // K1 | K2 | Vt
#define FL_SMEM_BYTES ((2 * 128 * QS2 + 2 * FL_STAGE) * 2)   // 92160

__device__ __forceinline__ void fl_load_kv(uint32_t sb, int st, int kt, int tid,
                                           const __half* K1g,
                                           const __half* K2g,
                                           const __half* Vg) {
    int r = tid >> 2, qd = tid & 3;   // row 0..63, 16-elem quarter
    uint32_t base = sb + (uint32_t)(FL_ST0 + st * FL_STAGE) * 2;
    uint32_t o = (uint32_t)(r * QS2 + qd * 16) * 2;
    const __half* k1 = K1g + (size_t)(kt * 64 + r) * DD + qd * 16;
    const __half* k2 = K2g + (size_t)(kt * 64 + r) * DD + qd * 16;
    const __half* vv = Vg + (size_t)r * TT + kt * 64 + qd * 16;
#pragma unroll
    for (int j = 0; j < 2; j++) {
        CP16(base + o + j * 16, k1 + j * 8);
        CP16(base + FL_KV * 2 + o + j * 16, k2 + j * 8);
        CP16(base + 2 * FL_KV * 2 + o + j * 16, vv + j * 8);
    }
}

// one stream: S = Q K^T (fp16), online softmax, O += P V (fp16)
__device__ __forceinline__ void fl_stream(uint32_t a_addr, uint32_t kstage, uint32_t vstage,
                                          uint32_t b_lane_b, int kt, bool need_mask,
                                          int row_g0, int lane,
                                          float O[8][4], float* mst, float* lst) {
    float acc[8][4];
#pragma unroll
    for (int nb = 0; nb < 8; nb++)
#pragma unroll
        for (int j = 0; j < 4; j++) acc[nb][j] = 0.f;

    // S = Q K^T, 4 k16 steps over D=64
#pragma unroll
    for (int s = 0; s < 4; s++) {
        uint32_t af[4];
        LDSM_X4(af[0], af[1], af[2], af[3], a_addr + s * 32);
#pragma unroll
        for (int nt2 = 0; nt2 < 4; nt2++) {
            uint32_t bf[4];
            LDSM_X4(bf[0], bf[1], bf[2], bf[3],
                    kstage + b_lane_b + (uint32_t)(nt2 * 16 * QS2 + s * 16) * 2);
            MMAH16816(acc[2 * nt2],     af, (&bf[0]));
            MMAH16816(acc[2 * nt2 + 1], af, (&bf[2]));
        }
    }

    // scale + causal mask
#pragma unroll
    for (int nb = 0; nb < 8; nb++)
#pragma unroll
        for (int j = 0; j < 4; j++) {
            float v = acc[nb][j] * 0.125f;
            if (need_mask) {
                int col = kt * 64 + nb * 8 + 2 * (lane & 3) + (j & 1);
                int row = row_g0 + ((j >> 1) << 3);
                if (col > row) v = -1e30f;
            }
            acc[nb][j] = v;
        }

    // online softmax (rows r and r+8)
    float mx0 = -1e30f, mx1 = -1e30f;
#pragma unroll
    for (int nb = 0; nb < 8; nb++) {
        mx0 = fmaxf(mx0, fmaxf(acc[nb][0], acc[nb][1]));
        mx1 = fmaxf(mx1, fmaxf(acc[nb][2], acc[nb][3]));
    }
    mx0 = fmaxf(mx0, __shfl_xor_sync(0xffffffffu, mx0, 1));
    mx0 = fmaxf(mx0, __shfl_xor_sync(0xffffffffu, mx0, 2));
    mx1 = fmaxf(mx1, __shfl_xor_sync(0xffffffffu, mx1, 1));
    mx1 = fmaxf(mx1, __shfl_xor_sync(0xffffffffu, mx1, 2));
    float mn0 = fmaxf(mst[0], mx0), mn1 = fmaxf(mst[1], mx1);
    float al0 = __expf(mst[0] - mn0), al1 = __expf(mst[1] - mn1);
    float s0 = 0.f, s1 = 0.f;
#pragma unroll
    for (int nb = 0; nb < 8; nb++) {
        acc[nb][0] = __expf(acc[nb][0] - mn0);
        acc[nb][1] = __expf(acc[nb][1] - mn0);
        acc[nb][2] = __expf(acc[nb][2] - mn1);
        acc[nb][3] = __expf(acc[nb][3] - mn1);
        s0 += acc[nb][0] + acc[nb][1];
        s1 += acc[nb][2] + acc[nb][3];
    }
    s0 += __shfl_xor_sync(0xffffffffu, s0, 1);
    s0 += __shfl_xor_sync(0xffffffffu, s0, 2);
    s1 += __shfl_xor_sync(0xffffffffu, s1, 1);
    s1 += __shfl_xor_sync(0xffffffffu, s1, 2);
    lst[0] = lst[0] * al0 + s0;
    lst[1] = lst[1] * al1 + s1;
    mst[0] = mn0;
    mst[1] = mn1;
#pragma unroll
    for (int nb = 0; nb < 8; nb++) {
        O[nb][0] *= al0; O[nb][1] *= al0;
        O[nb][2] *= al1; O[nb][3] *= al1;
    }

    // O += P V (register-direct fp16 P fragments)
#pragma unroll
    for (int s = 0; s < 4; s++) {
        uint32_t ah[4];
        ah[0] = packh(acc[2 * s][0],     acc[2 * s][1]);
        ah[1] = packh(acc[2 * s][2],     acc[2 * s][3]);
        ah[2] = packh(acc[2 * s + 1][0], acc[2 * s + 1][1]);
        ah[3] = packh(acc[2 * s + 1][2], acc[2 * s + 1][3]);
#pragma unroll
        for (int nt2 = 0; nt2 < 4; nt2++) {
            uint32_t bv[4];
            LDSM_X4(bv[0], bv[1], bv[2], bv[3],
                    vstage + b_lane_b + (uint32_t)(nt2 * 16 * QS2 + s * 16) * 2);
            MMAH16816(O[2 * nt2],     ah, (&bv[0]));
            MMAH16816(O[2 * nt2 + 1], ah, (&bv[2]));
        }
    }
}

__global__ void __launch_bounds__(256) flash_mma(
    const __half* __restrict__ Q1f, const __half* __restrict__ Q2f,
    const __half* __restrict__ K1f, const __half* __restrict__ K2f,
    const __half* __restrict__ Vtg, const float* __restrict__ lam_p,
    __nv_bfloat16* __restrict__ Ab) {
    extern __shared__ __half sfb[];
    const uint32_t sb = smem_u32(sfb);
    const int tid = threadIdx.x, wid = tid >> 5, lane = tid & 31;
    const int qrev = gridDim.x - 1 - blockIdx.x;    // heavy CTAs first
    const int q0 = qrev * 128;
    const int h = blockIdx.y, b = blockIdx.z;
    const int bh = b * HH + h;
    const int nkv = 2 * qrev + 2;

    const __half* Q1g = Q1f + ((size_t)bh * TT + q0) * DD;
    const __half* Q2g = Q2f + ((size_t)bh * TT + q0) * DD;
    const __half* K1g = K1f + (size_t)bh * TT * DD;
    const __half* K2g = K2f + (size_t)bh * TT * DD;
    const __half* Vg  = Vtg + (size_t)bh * DD * TT;

    // Q tiles via cp.async: 128 rows x 64 fp16
    {
        int row = tid >> 1, seg = (tid & 1) * 32;
        uint32_t d1 = sb + (uint32_t)(FL_Q1 + row * QS2 + seg) * 2;
        uint32_t d2 = sb + (uint32_t)(FL_Q2 + row * QS2 + seg) * 2;
        const __half* s1 = Q1g + row * DD + seg;
        const __half* s2 = Q2g + row * DD + seg;
#pragma unroll
        for (int j = 0; j < 4; j++) { CP16(d1 + j * 16, s1 + j * 8); CP16(d2 + j * 16, s2 + j * 8); }
    }
    fl_load_kv(sb, 0, 0, tid, K1g, K2g, Vg);
    CP_COMMIT();

    float O1[8][4], O2[8][4];
#pragma unroll
    for (int nb = 0; nb < 8; nb++)
#pragma unroll
        for (int j = 0; j < 4; j++) { O1[nb][j] = 0.f; O2[nb][j] = 0.f; }
    float m1[2] = {-1e30f, -1e30f}, l1[2] = {0.f, 0.f};
    float m2[2] = {-1e30f, -1e30f}, l2[2] = {0.f, 0.f};

    const int row_g0 = q0 + wid * 16 + (lane >> 2);
    const uint32_t a_lane = (uint32_t)((lane & 15) * QS2 + (lane >> 4) * 8) * 2;
    const uint32_t aQ1 = sb + (uint32_t)(FL_Q1 + wid * 16 * QS2) * 2 + a_lane;
    const uint32_t aQ2 = sb + (uint32_t)(FL_Q2 + wid * 16 * QS2) * 2 + a_lane;
    const uint32_t b_lane_b = (uint32_t)((((lane >> 4) & 1) * 8 + (lane & 7)) * QS2 +
                                         ((lane >> 3) & 1) * 8) * 2;

    for (int kt = 0; kt < nkv; kt++) {
        if (kt + 1 < nkv) {
            fl_load_kv(sb, (kt + 1) & 1, kt + 1, tid, K1g, K2g, Vg);
            CP_COMMIT();
            CP_WAIT(1);
        } else {
            CP_WAIT(0);
        }
        __syncthreads();
        const uint32_t st = sb + (uint32_t)(FL_ST0 + (kt & 1) * FL_STAGE) * 2;
        const bool msk = (kt >= nkv - 2);
        fl_stream(aQ1, st,             st + 2 * FL_KV * 2, b_lane_b, kt, msk, row_g0, lane, O1, m1, l1);
        fl_stream(aQ2, st + FL_KV * 2, st + 2 * FL_KV * 2, b_lane_b, kt, msk, row_g0, lane, O2, m2, l2);
        __syncthreads();
    }

    // epilogue: out = O1/l1 - lam*O2/l2, write split-bf16 [hi|lo] into Ab
    float lamv = fminf(fmaxf(lam_p[h], 0.f), 1.f);
    float i10 = 1.f / l1[0], i11 = 1.f / l1[1];
    float i20 = lamv / l2[0], i21 = lamv / l2[1];
    const int row0 = q0 + wid * 16 + (lane >> 2);
    const int colb = h * 64 + 2 * (lane & 3);
    size_t rb0 = (size_t)(b * TT + row0) * KW;
    size_t rb1 = (size_t)(b * TT + row0 + 8) * KW;
#pragma unroll
    for (int nb = 0; nb < 8; nb++) {
        int col = colb + nb * 8;
        float x0 = O1[nb][0] * i10 - O2[nb][0] * i20;
        float x1 = O1[nb][1] * i10 - O2[nb][1] * i20;
        float y0 = O1[nb][2] * i11 - O2[nb][2] * i21;
        float y1 = O1[nb][3] * i11 - O2[nb][3] * i21;
        uint32_t hx = packbf(x0, x1);
        __nv_bfloat162 hv = *(__nv_bfloat162*)&hx;
        float2 hf = __bfloat1622float2(hv);
        uint32_t lx = packbf(x0 - hf.x, x1 - hf.y);
        *(uint32_t*)&Ab[rb0 + col] = hx;
        *(uint32_t*)&Ab[rb0 + 1024 + col] = lx;
        uint32_t hy = packbf(y0, y1);
        __nv_bfloat162 hv2 = *(__nv_bfloat162*)&hy;
        float2 hf2 = __bfloat1622float2(hv2);
        uint32_t ly = packbf(y0 - hf2.x, y1 - hf2.y);
        *(uint32_t*)&Ab[rb1 + col] = hy;
        *(uint32_t*)&Ab[rb1 + 1024 + col] = ly;
    }
}

// ---------------- launch ----------------
extern "C" void kernel_launch(void* const* d_in, const int* in_sizes, int n_in,
                              void* d_out, int out_size) {
    const float* x    = (const float*)d_in[0];
    const float* Wqkv = (const float*)d_in[2];
    const float* Wout = (const float*)d_in[3];
    const float* lam  = (const float*)d_in[4];
    float* out = (float*)d_out;

    __nv_bfloat16 *Ab = nullptr, *Bq = nullptr, *Bo = nullptr;
    __half *Q1f = nullptr, *Q2f = nullptr, *K1f = nullptr, *K2f = nullptr;
    __half *Vh = nullptr, *Vt = nullptr;
    cudaGetSymbolAddress((void**)&Ab,  g_Ab);
    cudaGetSymbolAddress((void**)&Bq,  g_Bq);
    cudaGetSymbolAddress((void**)&Bo,  g_Bo);
    cudaGetSymbolAddress((void**)&Q1f, g_Q1f);
    cudaGetSymbolAddress((void**)&Q2f, g_Q2f);
    cudaGetSymbolAddress((void**)&K1f, g_K1f);
    cudaGetSymbolAddress((void**)&K2f, g_K2f);
    cudaGetSymbolAddress((void**)&Vh,  g_Vh);
    cudaGetSymbolAddress((void**)&Vt,  g_Vt);

    cudaFuncSetAttribute(gemm_mma<0>, cudaFuncAttributeMaxDynamicSharedMemorySize, GEMM_SMEM);
    cudaFuncSetAttribute(gemm_mma<1>, cudaFuncAttributeMaxDynamicSharedMemorySize, GEMM_SMEM);
    cudaFuncSetAttribute(flash_mma, cudaFuncAttributeMaxDynamicSharedMemorySize, FL_SMEM_BYTES);

    // weight + input split conversions
    splitT<<<dim3(NQKV / 32, DM / 32), dim3(32, 8)>>>(Wqkv, Bq, NQKV);
    splitT<<<dim3(DM / 32, DM / 32), dim3(32, 8)>>>(Wout, Bo, DM);
    split_rows<<<(BT * DM + 255) / 256, 256>>>(x, Ab, BT * DM);

    // 1) QKV projection (bf16 3-combo, 32 warps/CTA) + fused fp16 fan-out
    gemm_mma<1><<<dim3(NQKV / 128, BT / 128), GT, GEMM_SMEM>>>(
        Ab, Bq, nullptr, NQKV, Q1f, Q2f, K1f, K2f, Vh);

    // 2) V transpose (fp16 -> fp16)
    v_transpose_h<<<dim3(TT / 64, BB * HH), 256>>>(Vh, Vt);

    // 3) dual flash attention (fp16 HMMA, unconstrained regs); writes split-bf16 attn into Ab
    flash_mma<<<dim3(TT / 128, HH, BB), 256, FL_SMEM_BYTES>>>(Q1f, Q2f, K1f, K2f, Vt, lam, Ab);

    // 4) output projection (bf16 3-combo, 32 warps/CTA), fp32 C
    gemm_mma<0><<<dim3(DM / 128, BT / 128), GT, GEMM_SMEM>>>(
        Ab, Bo, out, DM, nullptr, nullptr, nullptr, nullptr, nullptr);
}